// round 12
// baseline (speedup 1.0000x reference)
#include <cuda_runtime.h>
#include <cuda_fp16.h>
#include <cstdint>

#define L_SEQ  1024
#define DMODEL 1024
#define DINNER 2048
#define NH     32
#define HD     64
#define NST    64
#define CONVD  2176
#define DPROJ  4256

#define NCHUNK 8
#define CHLEN  128

// ---------------- scratch (static device globals; no allocations) ----------------
__device__ __align__(128) float g_zx [2 * L_SEQ * DPROJ];
__device__ __align__(128) float g_x  [2 * L_SEQ * DINNER];
__device__ __align__(128) float g_dtx[2 * L_SEQ * DINNER];
__device__ __align__(128) float g_dA [2 * L_SEQ * NH];
__device__ __align__(128) float g_Bv [2 * L_SEQ * NST];
__device__ __align__(128) float g_Cv [2 * L_SEQ * NST];
__device__ __align__(128) float g_y  [2 * L_SEQ * DINNER];   // n-half 0 partial (+corr)
__device__ __align__(128) float g_y2 [2 * L_SEQ * DINNER];   // n-half 1 partial
__device__ __align__(128) float g_ygn[2 * L_SEQ * DINNER];   // fp32 scratch (pre-norm)

// time-split scan scratch
__device__ __align__(128) float g_state[2 * 32 * NCHUNK * 4096];       // chunk end states
__device__ __align__(128) float g_carry[2 * 32 * (NCHUNK - 1) * 4096]; // carry-in chunks 1..7
__device__ __align__(128) float g_cp   [2 * 32 * L_SEQ];               // within-chunk cumprod

// fp16 mirrors for GEMM inputs
__device__ __align__(128) __half g_hWin  [2 * DPROJ * DMODEL];
__device__ __align__(128) __half g_hWoutF[DMODEL * DINNER];
__device__ __align__(128) __half g_hWoutB[DMODEL * DINNER];
__device__ __align__(128) __half g_hWout [DMODEL * 2 * DMODEL];
__device__ __align__(128) __half g_hu    [L_SEQ * DMODEL];
__device__ __align__(128) __half g_hygn  [2 * L_SEQ * DINNER];
__device__ __align__(128) __half g_hG    [L_SEQ * 2 * DMODEL];

// ---------------- helpers ----------------
__device__ __forceinline__ float silu_f(float v) { return v / (1.f + expf(-v)); }
__device__ __forceinline__ float softplus_f(float v) { return v > 20.f ? v : log1pf(expf(v)); }

// packed fp32x2 ops (sm_103a FFMA2 path — PTX-only)
typedef unsigned long long u64t;
__device__ __forceinline__ u64t pk2(float v) {
    u64t r; asm("mov.b64 %0, {%1, %1};" : "=l"(r) : "f"(v)); return r;
}
__device__ __forceinline__ u64t fma2(u64t a, u64t b, u64t c) {
    u64t d; asm("fma.rn.f32x2 %0, %1, %2, %3;" : "=l"(d) : "l"(a), "l"(b), "l"(c)); return d;
}
__device__ __forceinline__ u64t mul2(u64t a, u64t b) {
    u64t d; asm("mul.rn.f32x2 %0, %1, %2;" : "=l"(d) : "l"(a), "l"(b)); return d;
}
__device__ __forceinline__ float hadd2(u64t a) {
    float lo, hi; asm("mov.b64 {%0, %1}, %2;" : "=f"(lo), "=f"(hi) : "l"(a)); return lo + hi;
}

__device__ __forceinline__ void mma_f16(float* c, const uint32_t* a, uint32_t b0, uint32_t b1) {
    asm volatile(
        "mma.sync.aligned.m16n8k16.row.col.f32.f16.f16.f32 "
        "{%0,%1,%2,%3},{%4,%5,%6,%7},{%8,%9},{%0,%1,%2,%3};"
        : "+f"(c[0]), "+f"(c[1]), "+f"(c[2]), "+f"(c[3])
        : "r"(a[0]), "r"(a[1]), "r"(a[2]), "r"(a[3]), "r"(b0), "r"(b1));
}

__device__ __forceinline__ uint2 f4_to_h4(float4 v) {
    __half2 lo = __floats2half2_rn(v.x, v.y);
    __half2 hi = __floats2half2_rn(v.z, v.w);
    uint2 r;
    r.x = *reinterpret_cast<uint32_t*>(&lo);
    r.y = *reinterpret_cast<uint32_t*>(&hi);
    return r;
}

__device__ __forceinline__ uint32_t smem_u32(const void* p) {
    uint32_t a;
    asm("{ .reg .u64 t; cvta.to.shared.u64 t, %1; cvt.u32.u64 %0, t; }" : "=r"(a) : "l"(p));
    return a;
}
__device__ __forceinline__ uint32_t swz64(uint32_t o) { return o ^ ((o >> 3) & 0x30); }

#define CP16(dst, src) \
    asm volatile("cp.async.cg.shared.global [%0], [%1], 16;" :: "r"(dst), "l"(src) : "memory")
#define CP_COMMIT() asm volatile("cp.async.commit_group;" ::: "memory")
#define CP_WAIT2()  asm volatile("cp.async.wait_group 2;" ::: "memory")

#define LDSM4(r, addr) \
    asm volatile("ldmatrix.sync.aligned.m8n8.x4.shared.b16 {%0,%1,%2,%3}, [%4];" \
                 : "=r"((r)[0]), "=r"((r)[1]), "=r"((r)[2]), "=r"((r)[3]) : "r"(addr))

// ---------------- fp16 GEMM, 4-stage cp.async + ldmatrix ----------------
#define STG_BYTES 16384
#define GEMM_SMEM (4 * STG_BYTES)

__global__ __launch_bounds__(256, 2) void gemm_hp(
    const __half* __restrict__ A, int lda, int flip_z1,
    const __half* __restrict__ W0, const __half* __restrict__ W1, int ldw,
    float* __restrict__ C, int ldc, int M, int N, int K,
    long strideA, long strideC, int epi)
{
    extern __shared__ __align__(128) char smem[];
    const uint32_t sbase = smem_u32(smem);

    const int z = blockIdx.z;
    const __half* Ap = A + (size_t)z * strideA;
    const __half* W  = z ? W1 : W0;
    float* Cp = C + (size_t)z * strideC;
    const bool flipA = (flip_z1 && z == 1);

    const int tid  = threadIdx.x;
    const int warp = tid >> 5, lane = tid & 31;
    const int g = lane >> 2, tg = lane & 3;
    const int wm = warp >> 2, wn = warp & 3;
    const int mblk = blockIdx.y * 128;
    const int nblk = blockIdx.x * 128;
    const int m0 = wm * 64, n0 = wn * 32;

    uint32_t offA[4][2], offB[2][2];
    {
        int mrow = (lane & 7) + ((lane >> 3) & 1) * 8;
        int kcA  = lane >> 4;
#pragma unroll
        for (int mt = 0; mt < 4; mt++)
#pragma unroll
            for (int ks = 0; ks < 2; ks++)
                offA[mt][ks] = swz64((m0 + mt * 16 + mrow) * 64 + ks * 32 + kcA * 16);
        int nrow = (lane & 7) + (lane >> 4) * 8;
        int kcB  = (lane >> 3) & 1;
#pragma unroll
        for (int p = 0; p < 2; p++)
#pragma unroll
            for (int ks = 0; ks < 2; ks++)
                offB[p][ks] = swz64((n0 + p * 16 + nrow) * 64 + ks * 32 + kcB * 16) + 8192;
    }

    const int srow0 = tid >> 2,          spos0 = tid & 3;
    const int srow1 = (tid + 256) >> 2,  spos1 = (tid + 256) & 3;
    const uint32_t sd0 = swz64(srow0 * 64 + spos0 * 16);
    const uint32_t sd1 = swz64(srow1 * 64 + spos1 * 16);

    const int T = K / 32;

#define ISSUE(t_) do {                                                         \
        int kt = (t_) * 32;                                                    \
        uint32_t sb = sbase + ((t_) & 3) * STG_BYTES;                          \
        {   int gr = mblk + srow0; int rA = flipA ? (M - 1 - gr) : gr;         \
            CP16(sb + sd0, Ap + (size_t)rA * lda + kt + spos0 * 8);            \
            int gn = nblk + srow0; if (gn >= N) gn = N - 1;                    \
            CP16(sb + 8192 + sd0, W + (size_t)gn * ldw + kt + spos0 * 8); }    \
        {   int gr = mblk + srow1; int rA = flipA ? (M - 1 - gr) : gr;         \
            CP16(sb + sd1, Ap + (size_t)rA * lda + kt + spos1 * 8);            \
            int gn = nblk + srow1; if (gn >= N) gn = N - 1;                    \
            CP16(sb + 8192 + sd1, W + (size_t)gn * ldw + kt + spos1 * 8); }    \
    } while (0)

    ISSUE(0); CP_COMMIT();
    ISSUE(1); CP_COMMIT();
    ISSUE(2); CP_COMMIT();

    float acc[4][4][4];
#pragma unroll
    for (int i = 0; i < 4; i++)
#pragma unroll
        for (int j = 0; j < 4; j++)
#pragma unroll
            for (int r = 0; r < 4; r++) acc[i][j][r] = 0.f;

    for (int t = 0; t < T; t++) {
        CP_WAIT2();
        __syncthreads();
        const uint32_t sb = sbase + (t & 3) * STG_BYTES;

#pragma unroll
        for (int ks = 0; ks < 2; ks++) {
            uint32_t a[4][4], b[2][4];
#pragma unroll
            for (int mt = 0; mt < 4; mt++) LDSM4(a[mt], sb + offA[mt][ks]);
#pragma unroll
            for (int p = 0; p < 2; p++)    LDSM4(b[p], sb + offB[p][ks]);
#pragma unroll
            for (int mt = 0; mt < 4; mt++)
#pragma unroll
                for (int nt = 0; nt < 4; nt++)
                    mma_f16(acc[mt][nt], a[mt], b[nt >> 1][(nt & 1) * 2],
                            b[nt >> 1][(nt & 1) * 2 + 1]);
        }

        if (t + 3 < T) ISSUE(t + 3);
        CP_COMMIT();
    }

    if (epi == 0) {
#pragma unroll
        for (int mt = 0; mt < 4; mt++) {
#pragma unroll
            for (int nt = 0; nt < 4; nt++) {
                int row = mblk + m0 + mt * 16 + g;
                int col = nblk + n0 + nt * 8 + 2 * tg;
                if (col < N) {
                    Cp[(size_t)row * ldc + col]           = acc[mt][nt][0];
                    Cp[(size_t)(row + 8) * ldc + col]     = acc[mt][nt][2];
                }
                if (col + 1 < N) {
                    Cp[(size_t)row * ldc + col + 1]       = acc[mt][nt][1];
                    Cp[(size_t)(row + 8) * ldc + col + 1] = acc[mt][nt][3];
                }
            }
        }
    } else {
#pragma unroll
        for (int mt = 0; mt < 4; mt++) {
#pragma unroll
            for (int nt = 0; nt < 4; nt++) {
                int row = mblk + m0 + mt * 16 + g;
                int col = nblk + n0 + nt * 8 + 2 * tg;
                __half2 h0 = __floats2half2_rn(silu_f(acc[mt][nt][0]), silu_f(acc[mt][nt][1]));
                __half2 h1 = __floats2half2_rn(silu_f(acc[mt][nt][2]), silu_f(acc[mt][nt][3]));
                if (z == 0) {
                    *reinterpret_cast<__half2*>(&g_hG[(size_t)row * 2 * DMODEL + col])       = h0;
                    *reinterpret_cast<__half2*>(&g_hG[(size_t)(row + 8) * 2 * DMODEL + col]) = h1;
                } else {
                    *reinterpret_cast<__half2*>(&g_hG[(size_t)(L_SEQ - 1 - row) * 2 * DMODEL + DMODEL + col]) = h0;
                    *reinterpret_cast<__half2*>(&g_hG[(size_t)(L_SEQ - 9 - row) * 2 * DMODEL + DMODEL + col]) = h1;
                }
            }
        }
    }
}

// ---------------- fp32 -> fp16 conversion (weights + u), grid-stride ----------------
__global__ __launch_bounds__(256) void cvt6_kernel(
    const float* __restrict__ s0, const float* __restrict__ s1,
    const float* __restrict__ s2, const float* __restrict__ s3,
    const float* __restrict__ s4, const float* __restrict__ s5)
{
    const int stride = gridDim.x * blockDim.x;
    const int gid = blockIdx.x * blockDim.x + threadIdx.x;
    const float* srcs[6] = {s0, s1, s2, s3, s4, s5};
    __half* dsts[6] = {g_hWin, g_hWin + DPROJ * DMODEL, g_hWoutF, g_hWoutB, g_hWout, g_hu};
    const int cnts[6] = {DPROJ * DMODEL / 4, DPROJ * DMODEL / 4, DMODEL * DINNER / 4,
                         DMODEL * DINNER / 4, DMODEL * 2 * DMODEL / 4, L_SEQ * DMODEL / 4};
#pragma unroll
    for (int seg = 0; seg < 6; seg++) {
        const float4* src = reinterpret_cast<const float4*>(srcs[seg]);
        uint2* dst = reinterpret_cast<uint2*>(dsts[seg]);
        for (int i = gid; i < cnts[seg]; i += stride)
            dst[i] = f4_to_h4(src[i]);
    }
}

// ---------------- prep: causal dwconv + silu, dt softplus, dA, dtx ----------------
__global__ __launch_bounds__(256) void prep_kernel(
    const float* __restrict__ cw_f, const float* __restrict__ cb_f,
    const float* __restrict__ cw_b, const float* __restrict__ cb_b,
    const float* __restrict__ dtb_f, const float* __restrict__ dtb_b,
    const float* __restrict__ Alog_f, const float* __restrict__ Alog_b)
{
    const int l = blockIdx.x, dir = blockIdx.y, tid = threadIdx.x;
    const float* cw   = dir ? cw_b   : cw_f;
    const float* cb   = dir ? cb_b   : cb_f;
    const float* dtb  = dir ? dtb_b  : dtb_f;
    const float* Alog = dir ? Alog_b : Alog_f;

    const size_t base = (size_t)dir * L_SEQ + l;
    const float* zrow = g_zx + base * DPROJ;

    __shared__ float sdt[NH];
    if (tid < NH) {
        float dt = softplus_f(zrow[4224 + tid] + dtb[tid]);
        sdt[tid] = dt;
        g_dA[base * NH + tid] = expf(-expf(Alog[tid]) * dt);
    }
    __syncthreads();

    for (int c = tid; c < CONVD; c += 256) {
        float s = cb[c];
#pragma unroll
        for (int t = 0; t < 4; t++) {
            int lp = l - 3 + t;
            if (lp >= 0)
                s = fmaf(cw[c * 4 + t],
                         g_zx[((size_t)dir * L_SEQ + lp) * DPROJ + 2048 + c], s);
        }
        float v = silu_f(s);
        if (c < DINNER) {
            g_x[base * DINNER + c]   = v;
            g_dtx[base * DINNER + c] = sdt[c >> 6] * v;
        } else if (c < 2112) {
            g_Bv[base * NST + (c - 2048)] = v;
        } else {
            g_Cv[base * NST + (c - 2112)] = v;
        }
    }
}

// ---------------- pass 1: time-split scan, p-per-thread / n-in-registers ----------------
// grid (16 = [ns][ts], 16 head-pairs, 2 dirs) = 512 blocks, block 128 = 2 heads x 64 p.
// Each thread owns one p and 32 n (one ns-half) as 16 f32x2 register pairs.
#define SCH 16

__global__ __launch_bounds__(128) void scan_kernel()
{
    const int bx = blockIdx.x;
    const int ns = bx & 1, ts = bx >> 1;   // ts in 0..7
    const int hg = blockIdx.y, dir = blockIdx.z;
    const int tid = threadIdx.x;
    const int hl = tid >> 6, p = tid & 63;
    const int hh = hg * 2 + hl;

    __shared__ __align__(16) float sB[SCH][32], sC[SCH][32];
    __shared__ __align__(16) float sdt[SCH][128];
    __shared__ float sdA[SCH][2];

    u64t h[16];
#pragma unroll
    for (int j = 0; j < 16; j++) h[j] = 0ull;

    const size_t dbase = (size_t)dir * L_SEQ;
    const int nbase = ns * 32;
    float* yout = ns ? g_y2 : g_y;

    const int cstart = ts * CHLEN;
    for (int c0 = cstart; c0 < cstart + CHLEN; c0 += SCH) {
        {
            int s = tid >> 3, f = (tid & 7) << 2;
            *reinterpret_cast<float4*>(&sB[s][f]) =
                *reinterpret_cast<const float4*>(g_Bv + (dbase + c0 + s) * NST + nbase + f);
            *reinterpret_cast<float4*>(&sC[s][f]) =
                *reinterpret_cast<const float4*>(g_Cv + (dbase + c0 + s) * NST + nbase + f);
#pragma unroll
            for (int e = 0; e < 4; e++) {
                int idx = tid + e * 128;
                int s2 = idx >> 5, r = idx & 31;
                int h2 = r >> 4, pp = (r & 15) << 2;
                *reinterpret_cast<float4*>(&sdt[s2][h2 * 64 + pp]) =
                    *reinterpret_cast<const float4*>(
                        g_dtx + (dbase + c0 + s2) * DINNER + (hg * 2 + h2) * HD + pp);
            }
            if (tid < SCH * 2)
                sdA[tid >> 1][tid & 1] = g_dA[(dbase + c0 + (tid >> 1)) * NH + hg * 2 + (tid & 1)];
        }
        __syncthreads();

#pragma unroll
        for (int s = 0; s < SCH; s++) {
            const u64t dA2 = pk2(sdA[s][hl]);
            const u64t dt2 = pk2(sdt[s][hl * 64 + p]);
            const ulonglong2* Bp = reinterpret_cast<const ulonglong2*>(&sB[s][0]);
            const ulonglong2* Cq = reinterpret_cast<const ulonglong2*>(&sC[s][0]);
            u64t acc = 0ull;
#pragma unroll
            for (int j = 0; j < 8; j++) {
                ulonglong2 b2 = Bp[j], c2 = Cq[j];
                h[2 * j]     = fma2(h[2 * j],     dA2, mul2(dt2, b2.x));
                acc          = fma2(h[2 * j],     c2.x, acc);
                h[2 * j + 1] = fma2(h[2 * j + 1], dA2, mul2(dt2, b2.y));
                acc          = fma2(h[2 * j + 1], c2.y, acc);
            }
            yout[(dbase + c0 + s) * DINNER + hh * HD + p] = hadd2(acc);
        }
        __syncthreads();
    }

    // store end-of-chunk state: [dir][head][ts][ps][ns][pl][n32]
    {
        size_t stb = ((size_t)((dir * 32 + hh) * NCHUNK + ts) * 4 + (p >> 5) * 2 + ns) * 1024
                     + (p & 31) * 32;
#pragma unroll
        for (int j = 0; j < 8; j++) {
            ulonglong2 st; st.x = h[2 * j]; st.y = h[2 * j + 1];
            *reinterpret_cast<ulonglong2*>(&g_state[stb + j * 4]) = st;
        }
    }
}

// ---------------- pass 2: cumprods + chunk-carry combine (chunk = warp = 128 t) --------
__global__ __launch_bounds__(256) void chain_kernel()
{
    const int hh = blockIdx.x, dir = blockIdx.y;
    const int tid = threadIdx.x, lane = tid & 31, warp = tid >> 5;
    const size_t dbase = (size_t)dir * L_SEQ;
    __shared__ float wtot[NCHUNK];
    __shared__ float scA[NCHUNK];

    float inc[4];
    float s = 0.f;
#pragma unroll
    for (int j = 0; j < 4; j++) {
        float a = g_dA[(dbase + tid * 4 + j) * NH + hh];
        s += logf(a);
        inc[j] = s;
    }
    const float tot = s;
    float wsc = tot;
#pragma unroll
    for (int off = 1; off < 32; off <<= 1) {
        float v = __shfl_up_sync(0xffffffffu, wsc, off);
        if (lane >= off) wsc += v;
    }
    if (lane == 31) wtot[warp] = wsc;
    const float excl = wsc - tot;     // within-warp == within-chunk (chunk = warp)
    const size_t cpb = (size_t)(dir * 32 + hh) * L_SEQ;
#pragma unroll
    for (int j = 0; j < 4; j++)
        g_cp[cpb + tid * 4 + j] = expf(excl + inc[j]);
    __syncthreads();
    if (tid < NCHUNK) scA[tid] = expf(wtot[tid]);
    __syncthreads();

    const size_t sb = (size_t)(dir * 32 + hh) * NCHUNK * 4096;
    const size_t cb = (size_t)(dir * 32 + hh) * (NCHUNK - 1) * 4096;
    for (int e = 0; e < 16; e++) {
        int idx = tid + e * 256;
        float c = g_state[sb + idx];
        g_carry[cb + idx] = c;
#pragma unroll
        for (int k = 1; k < NCHUNK - 1; k++) {
            c = g_state[sb + (size_t)k * 4096 + idx] + scA[k] * c;
            g_carry[cb + (size_t)k * 4096 + idx] = c;
        }
    }
}

// ---------------- pass 3: correction y[t] += cp[t] * (C[t] . carry) ----------------
// grid (14 tiles = [chunk 1..7][2 t-subtiles of 64], 32 heads, 2 dirs), block 256.
__global__ __launch_bounds__(256) void corr_kernel()
{
    const int tile = blockIdx.x;
    const int hh = blockIdx.y, dir = blockIdx.z;
    const int chunk = 1 + (tile >> 1);
    const int t0 = chunk * CHLEN + (tile & 1) * 64;
    const int tid = threadIdx.x;
    const size_t dbase = (size_t)dir * L_SEQ;

    __shared__ float sC[64 * 65];
    __shared__ __align__(16) float sCar[64 * 68];
    __shared__ float scp[64];

    const size_t cb = (size_t)(dir * 32 + hh) * (NCHUNK - 1) * 4096
                      + (size_t)(chunk - 1) * 4096;
#pragma unroll
    for (int e = 0; e < 16; e++) {
        int idx = tid + e * 256;
        int ps = idx >> 11, nsb = (idx >> 10) & 1, pl = (idx >> 5) & 31, nl = idx & 31;
        sCar[(nsb * 32 + nl) * 68 + ps * 32 + pl] = g_carry[cb + idx];
    }
#pragma unroll
    for (int e = 0; e < 4; e++) {
        int f = tid + e * 256;
        int tl = f >> 4, nq = (f & 15) * 4;
        float4 v = *reinterpret_cast<const float4*>(g_Cv + (dbase + t0 + tl) * NST + nq);
        sC[tl * 65 + nq]     = v.x; sC[tl * 65 + nq + 1] = v.y;
        sC[tl * 65 + nq + 2] = v.z; sC[tl * 65 + nq + 3] = v.w;
    }
    if (tid < 64) scp[tid] = g_cp[(size_t)(dir * 32 + hh) * L_SEQ + t0 + tid];
    __syncthreads();

    const int tq = tid >> 4, pq = tid & 15;
    u64t acc[4][2];
#pragma unroll
    for (int i = 0; i < 4; i++) { acc[i][0] = 0ull; acc[i][1] = 0ull; }

#pragma unroll 4
    for (int n = 0; n < 64; n++) {
        ulonglong2 car = *reinterpret_cast<const ulonglong2*>(&sCar[n * 68 + pq * 4]);
#pragma unroll
        for (int j = 0; j < 4; j++) {
            u64t cv = pk2(sC[(tq * 4 + j) * 65 + n]);
            acc[j][0] = fma2(cv, car.x, acc[j][0]);
            acc[j][1] = fma2(cv, car.y, acc[j][1]);
        }
    }

#pragma unroll
    for (int j = 0; j < 4; j++) {
        int t = t0 + tq * 4 + j;
        float cp = scp[tq * 4 + j];
        float a0, a1, a2, a3;
        asm("mov.b64 {%0,%1}, %2;" : "=f"(a0), "=f"(a1) : "l"(acc[j][0]));
        asm("mov.b64 {%0,%1}, %2;" : "=f"(a2), "=f"(a3) : "l"(acc[j][1]));
        float4* yp = reinterpret_cast<float4*>(g_y + (dbase + t) * DINNER + hh * 64 + pq * 4);
        float4 v = *yp;
        v.x += cp * a0; v.y += cp * a1; v.z += cp * a2; v.w += cp * a3;
        *yp = v;
    }
}

// ---------------- gate: (y0+y1) + D*x, *silu(z), rmsnorm, *norm_w -> fp16 ----------------
__global__ __launch_bounds__(256) void gate_kernel(
    const float* __restrict__ D_f, const float* __restrict__ D_b,
    const float* __restrict__ nw_f, const float* __restrict__ nw_b)
{
    const int l = blockIdx.x, dir = blockIdx.y, tid = threadIdx.x;
    const float* Dp = dir ? D_b : D_f;
    const float* nw = dir ? nw_b : nw_f;
    const size_t base = (size_t)dir * L_SEQ + l;

    const float4* y4  = reinterpret_cast<const float4*>(g_y  + base * DINNER);
    const float4* y24 = reinterpret_cast<const float4*>(g_y2 + base * DINNER);
    const float4* x4  = reinterpret_cast<const float4*>(g_x  + base * DINNER);
    const float4* z4  = reinterpret_cast<const float4*>(g_zx + base * DPROJ);
    float4* o4 = reinterpret_cast<float4*>(g_ygn + base * DINNER);
    uint2* h4 = reinterpret_cast<uint2*>(g_hygn + base * DINNER);

    float ss = 0.f;
#pragma unroll
    for (int it = 0; it < 2; it++) {
        int c4 = tid + it * 256;
        float dd = Dp[c4 >> 4];
        float4 a = y4[c4], b = y24[c4], x = x4[c4], z = z4[c4];
        float4 r;
        r.x = (a.x + b.x + dd * x.x) * silu_f(z.x);
        r.y = (a.y + b.y + dd * x.y) * silu_f(z.y);
        r.z = (a.z + b.z + dd * x.z) * silu_f(z.z);
        r.w = (a.w + b.w + dd * x.w) * silu_f(z.w);
        o4[c4] = r;
        ss += r.x * r.x + r.y * r.y + r.z * r.z + r.w * r.w;
    }
    __shared__ float red[8];
#pragma unroll
    for (int o = 16; o; o >>= 1) ss += __shfl_xor_sync(0xffffffffu, ss, o);
    if ((tid & 31) == 0) red[tid >> 5] = ss;
    __syncthreads();
    if (tid < 8) {
        float v = red[tid];
#pragma unroll
        for (int o = 4; o; o >>= 1) v += __shfl_xor_sync(0xffu, v, o);
        if (tid == 0) red[0] = v;
    }
    __syncthreads();
    const float scale = rsqrtf(red[0] * (1.f / DINNER) + 1e-5f);
    const float4* nw4 = reinterpret_cast<const float4*>(nw);
#pragma unroll
    for (int it = 0; it < 2; it++) {
        int c4 = tid + it * 256;
        float4 r = o4[c4], w = nw4[c4];
        r.x *= scale * w.x; r.y *= scale * w.y; r.z *= scale * w.z; r.w *= scale * w.w;
        h4[c4] = f4_to_h4(r);
    }
}

// ---------------- launch ----------------
extern "C" void kernel_launch(void* const* d_in, const int* in_sizes, int n_in,
                              void* d_out, int out_size)
{
    const float* u         = (const float*)d_in[0];
    const float* W_in_f    = (const float*)d_in[1];
    const float* W_in_b    = (const float*)d_in[2];
    const float* conv_w_f  = (const float*)d_in[3];
    const float* conv_b_f  = (const float*)d_in[4];
    const float* conv_w_b  = (const float*)d_in[5];
    const float* conv_b_b  = (const float*)d_in[6];
    const float* dt_bias_f = (const float*)d_in[7];
    const float* dt_bias_b = (const float*)d_in[8];
    const float* A_log_f   = (const float*)d_in[9];
    const float* A_log_b   = (const float*)d_in[10];
    const float* D_f       = (const float*)d_in[11];
    const float* D_b       = (const float*)d_in[12];
    const float* norm_w_f  = (const float*)d_in[13];
    const float* norm_w_b  = (const float*)d_in[14];
    const float* W_out_f   = (const float*)d_in[15];
    const float* W_out_b   = (const float*)d_in[16];
    const float* W_out     = (const float*)d_in[17];

    static int attr_done = 0;
    if (!attr_done) {
        cudaFuncSetAttribute(gemm_hp, cudaFuncAttributeMaxDynamicSharedMemorySize, GEMM_SMEM);
        attr_done = 1;
    }

    float *zx;
    __half *hWin, *hWoutF, *hWoutB, *hWout, *hu, *hygn, *hG;
    cudaGetSymbolAddress((void**)&zx,     g_zx);
    cudaGetSymbolAddress((void**)&hWin,   g_hWin);
    cudaGetSymbolAddress((void**)&hWoutF, g_hWoutF);
    cudaGetSymbolAddress((void**)&hWoutB, g_hWoutB);
    cudaGetSymbolAddress((void**)&hWout,  g_hWout);
    cudaGetSymbolAddress((void**)&hu,     g_hu);
    cudaGetSymbolAddress((void**)&hygn,   g_hygn);
    cudaGetSymbolAddress((void**)&hG,     g_hG);

    // 0) fp32 -> fp16 conversions (weights + u)
    cvt6_kernel<<<1024, 256>>>(W_in_f, W_in_b, W_out_f, W_out_b, W_out, u);

    // 1) in_proj, both directions (z=dir; flip A rows when z==1)
    gemm_hp<<<dim3((DPROJ + 127) / 128, L_SEQ / 128, 2), 256, GEMM_SMEM>>>(
        hu, DMODEL, 1, hWin, hWin + (size_t)DPROJ * DMODEL, DMODEL, zx, DPROJ,
        L_SEQ, DPROJ, DMODEL, 0, (long)L_SEQ * DPROJ, 0);

    // 2) conv + silu + dt/dA/dtx
    prep_kernel<<<dim3(L_SEQ, 2), 256>>>(conv_w_f, conv_b_f, conv_w_b, conv_b_b,
                                         dt_bias_f, dt_bias_b, A_log_f, A_log_b);

    // 3) time-split scan: local chunks (p-per-thread, 8 chunks), carry chain, correction
    scan_kernel<<<dim3(16, 16, 2), 128>>>();
    chain_kernel<<<dim3(NH, 2), 256>>>();
    corr_kernel<<<dim3(14, NH, 2), 256>>>();

    // 4) gate + rmsnorm -> fp16 ygn
    gate_kernel<<<dim3(L_SEQ, 2), 256>>>(D_f, D_b, norm_w_f, norm_w_b);

    // 5) out projections, epi=1 fuses silu + concat + flip into g_hG
    gemm_hp<<<dim3(DMODEL / 128, L_SEQ / 128, 2), 256, GEMM_SMEM>>>(
        hygn, DINNER, 0, hWoutF, hWoutB, DINNER, zx /*unused*/, DMODEL,
        L_SEQ, DMODEL, DINNER, (long)L_SEQ * DINNER, 0, 1);

    // 6) final projection
    gemm_hp<<<dim3(DMODEL / 128, L_SEQ / 128, 1), 256, GEMM_SMEM>>>(
        hG, 2 * DMODEL, 0, hWout, hWout, 2 * DMODEL, (float*)d_out, DMODEL,
        L_SEQ, DMODEL, 2 * DMODEL, 0, 0, 0);
}

// round 13
// speedup vs baseline: 1.0813x; 1.0813x over previous
#include <cuda_runtime.h>
#include <cuda_fp16.h>
#include <cstdint>

#define L_SEQ  1024
#define DMODEL 1024
#define DINNER 2048
#define NH     32
#define HD     64
#define NST    64
#define CONVD  2176
#define DPROJ  4256

// ---------------- scratch (static device globals; no allocations) ----------------
__device__ __align__(128) float g_zx [2 * L_SEQ * DPROJ];
__device__ __align__(128) float g_x  [2 * L_SEQ * DINNER];
__device__ __align__(128) float g_dtx[2 * L_SEQ * DINNER];
__device__ __align__(128) float g_dA [2 * L_SEQ * NH];
__device__ __align__(128) float g_Bv [2 * L_SEQ * NST];
__device__ __align__(128) float g_Cv [2 * L_SEQ * NST];
__device__ __align__(128) float g_y  [2 * L_SEQ * DINNER];   // n-quarter 0 partial (+corr)
__device__ __align__(128) float g_y2 [2 * L_SEQ * DINNER];   // n-quarter 1 partial
__device__ __align__(128) float g_y3 [2 * L_SEQ * DINNER];   // n-quarter 2 partial
__device__ __align__(128) float g_y4 [2 * L_SEQ * DINNER];   // n-quarter 3 partial
__device__ __align__(128) float g_ygn[2 * L_SEQ * DINNER];   // fp32 scratch (pre-norm)

// time-split scan scratch (4 chunks of 256)
__device__ __align__(128) float g_state[2 * 32 * 4 * 4096];  // [dir][head][ts][ps][nsb][pl][n32]
__device__ __align__(128) float g_carry[2 * 32 * 3 * 4096];  // carry-in for chunks 1..3
__device__ __align__(128) float g_cp   [2 * 32 * L_SEQ];     // within-chunk cumprod of dA

// fp16 mirrors for GEMM inputs
__device__ __align__(128) __half g_hWin  [2 * DPROJ * DMODEL];
__device__ __align__(128) __half g_hWoutF[DMODEL * DINNER];
__device__ __align__(128) __half g_hWoutB[DMODEL * DINNER];
__device__ __align__(128) __half g_hWout [DMODEL * 2 * DMODEL];
__device__ __align__(128) __half g_hu    [L_SEQ * DMODEL];
__device__ __align__(128) __half g_hygn  [2 * L_SEQ * DINNER];
__device__ __align__(128) __half g_hG    [L_SEQ * 2 * DMODEL];

// ---------------- helpers ----------------
__device__ __forceinline__ float silu_f(float v) { return v / (1.f + expf(-v)); }
__device__ __forceinline__ float softplus_f(float v) { return v > 20.f ? v : log1pf(expf(v)); }

// packed fp32x2 ops (sm_103a FFMA2 path — PTX-only)
typedef unsigned long long u64t;
__device__ __forceinline__ u64t pk2(float v) {
    u64t r; asm("mov.b64 %0, {%1, %1};" : "=l"(r) : "f"(v)); return r;
}
__device__ __forceinline__ u64t fma2(u64t a, u64t b, u64t c) {
    u64t d; asm("fma.rn.f32x2 %0, %1, %2, %3;" : "=l"(d) : "l"(a), "l"(b), "l"(c)); return d;
}
__device__ __forceinline__ u64t mul2(u64t a, u64t b) {
    u64t d; asm("mul.rn.f32x2 %0, %1, %2;" : "=l"(d) : "l"(a), "l"(b)); return d;
}
__device__ __forceinline__ float hadd2(u64t a) {
    float lo, hi; asm("mov.b64 {%0, %1}, %2;" : "=f"(lo), "=f"(hi) : "l"(a)); return lo + hi;
}

__device__ __forceinline__ void mma_f16(float* c, const uint32_t* a, uint32_t b0, uint32_t b1) {
    asm volatile(
        "mma.sync.aligned.m16n8k16.row.col.f32.f16.f16.f32 "
        "{%0,%1,%2,%3},{%4,%5,%6,%7},{%8,%9},{%0,%1,%2,%3};"
        : "+f"(c[0]), "+f"(c[1]), "+f"(c[2]), "+f"(c[3])
        : "r"(a[0]), "r"(a[1]), "r"(a[2]), "r"(a[3]), "r"(b0), "r"(b1));
}

__device__ __forceinline__ uint2 f4_to_h4(float4 v) {
    __half2 lo = __floats2half2_rn(v.x, v.y);
    __half2 hi = __floats2half2_rn(v.z, v.w);
    uint2 r;
    r.x = *reinterpret_cast<uint32_t*>(&lo);
    r.y = *reinterpret_cast<uint32_t*>(&hi);
    return r;
}

__device__ __forceinline__ uint32_t smem_u32(const void* p) {
    uint32_t a;
    asm("{ .reg .u64 t; cvta.to.shared.u64 t, %1; cvt.u32.u64 %0, t; }" : "=r"(a) : "l"(p));
    return a;
}
__device__ __forceinline__ uint32_t swz64(uint32_t o) { return o ^ ((o >> 3) & 0x30); }

#define CP16(dst, src) \
    asm volatile("cp.async.cg.shared.global [%0], [%1], 16;" :: "r"(dst), "l"(src) : "memory")
#define CP_COMMIT() asm volatile("cp.async.commit_group;" ::: "memory")
#define CP_WAIT2()  asm volatile("cp.async.wait_group 2;" ::: "memory")

#define LDSM4(r, addr) \
    asm volatile("ldmatrix.sync.aligned.m8n8.x4.shared.b16 {%0,%1,%2,%3}, [%4];" \
                 : "=r"((r)[0]), "=r"((r)[1]), "=r"((r)[2]), "=r"((r)[3]) : "r"(addr))

// ---------------- fp16 GEMM, 4-stage cp.async + ldmatrix ----------------
#define STG_BYTES 16384
#define GEMM_SMEM (4 * STG_BYTES)

__global__ __launch_bounds__(256, 2) void gemm_hp(
    const __half* __restrict__ A, int lda, int flip_z1,
    const __half* __restrict__ W0, const __half* __restrict__ W1, int ldw,
    float* __restrict__ C, int ldc, int M, int N, int K,
    long strideA, long strideC, int epi)
{
    extern __shared__ __align__(128) char smem[];
    const uint32_t sbase = smem_u32(smem);

    const int z = blockIdx.z;
    const __half* Ap = A + (size_t)z * strideA;
    const __half* W  = z ? W1 : W0;
    float* Cp = C + (size_t)z * strideC;
    const bool flipA = (flip_z1 && z == 1);

    const int tid  = threadIdx.x;
    const int warp = tid >> 5, lane = tid & 31;
    const int g = lane >> 2, tg = lane & 3;
    const int wm = warp >> 2, wn = warp & 3;
    const int mblk = blockIdx.y * 128;
    const int nblk = blockIdx.x * 128;
    const int m0 = wm * 64, n0 = wn * 32;

    uint32_t offA[4][2], offB[2][2];
    {
        int mrow = (lane & 7) + ((lane >> 3) & 1) * 8;
        int kcA  = lane >> 4;
#pragma unroll
        for (int mt = 0; mt < 4; mt++)
#pragma unroll
            for (int ks = 0; ks < 2; ks++)
                offA[mt][ks] = swz64((m0 + mt * 16 + mrow) * 64 + ks * 32 + kcA * 16);
        int nrow = (lane & 7) + (lane >> 4) * 8;
        int kcB  = (lane >> 3) & 1;
#pragma unroll
        for (int p = 0; p < 2; p++)
#pragma unroll
            for (int ks = 0; ks < 2; ks++)
                offB[p][ks] = swz64((n0 + p * 16 + nrow) * 64 + ks * 32 + kcB * 16) + 8192;
    }

    const int srow0 = tid >> 2,          spos0 = tid & 3;
    const int srow1 = (tid + 256) >> 2,  spos1 = (tid + 256) & 3;
    const uint32_t sd0 = swz64(srow0 * 64 + spos0 * 16);
    const uint32_t sd1 = swz64(srow1 * 64 + spos1 * 16);

    const int T = K / 32;

#define ISSUE(t_) do {                                                         \
        int kt = (t_) * 32;                                                    \
        uint32_t sb = sbase + ((t_) & 3) * STG_BYTES;                          \
        {   int gr = mblk + srow0; int rA = flipA ? (M - 1 - gr) : gr;         \
            CP16(sb + sd0, Ap + (size_t)rA * lda + kt + spos0 * 8);            \
            int gn = nblk + srow0; if (gn >= N) gn = N - 1;                    \
            CP16(sb + 8192 + sd0, W + (size_t)gn * ldw + kt + spos0 * 8); }    \
        {   int gr = mblk + srow1; int rA = flipA ? (M - 1 - gr) : gr;         \
            CP16(sb + sd1, Ap + (size_t)rA * lda + kt + spos1 * 8);            \
            int gn = nblk + srow1; if (gn >= N) gn = N - 1;                    \
            CP16(sb + 8192 + sd1, W + (size_t)gn * ldw + kt + spos1 * 8); }    \
    } while (0)

    ISSUE(0); CP_COMMIT();
    ISSUE(1); CP_COMMIT();
    ISSUE(2); CP_COMMIT();

    float acc[4][4][4];
#pragma unroll
    for (int i = 0; i < 4; i++)
#pragma unroll
        for (int j = 0; j < 4; j++)
#pragma unroll
            for (int r = 0; r < 4; r++) acc[i][j][r] = 0.f;

    for (int t = 0; t < T; t++) {
        CP_WAIT2();
        __syncthreads();
        const uint32_t sb = sbase + (t & 3) * STG_BYTES;

#pragma unroll
        for (int ks = 0; ks < 2; ks++) {
            uint32_t a[4][4], b[2][4];
#pragma unroll
            for (int mt = 0; mt < 4; mt++) LDSM4(a[mt], sb + offA[mt][ks]);
#pragma unroll
            for (int p = 0; p < 2; p++)    LDSM4(b[p], sb + offB[p][ks]);
#pragma unroll
            for (int mt = 0; mt < 4; mt++)
#pragma unroll
                for (int nt = 0; nt < 4; nt++)
                    mma_f16(acc[mt][nt], a[mt], b[nt >> 1][(nt & 1) * 2],
                            b[nt >> 1][(nt & 1) * 2 + 1]);
        }

        if (t + 3 < T) ISSUE(t + 3);
        CP_COMMIT();
    }

    if (epi == 0) {
#pragma unroll
        for (int mt = 0; mt < 4; mt++) {
#pragma unroll
            for (int nt = 0; nt < 4; nt++) {
                int row = mblk + m0 + mt * 16 + g;
                int col = nblk + n0 + nt * 8 + 2 * tg;
                if (col < N) {
                    Cp[(size_t)row * ldc + col]           = acc[mt][nt][0];
                    Cp[(size_t)(row + 8) * ldc + col]     = acc[mt][nt][2];
                }
                if (col + 1 < N) {
                    Cp[(size_t)row * ldc + col + 1]       = acc[mt][nt][1];
                    Cp[(size_t)(row + 8) * ldc + col + 1] = acc[mt][nt][3];
                }
            }
        }
    } else {
#pragma unroll
        for (int mt = 0; mt < 4; mt++) {
#pragma unroll
            for (int nt = 0; nt < 4; nt++) {
                int row = mblk + m0 + mt * 16 + g;
                int col = nblk + n0 + nt * 8 + 2 * tg;
                __half2 h0 = __floats2half2_rn(silu_f(acc[mt][nt][0]), silu_f(acc[mt][nt][1]));
                __half2 h1 = __floats2half2_rn(silu_f(acc[mt][nt][2]), silu_f(acc[mt][nt][3]));
                if (z == 0) {
                    *reinterpret_cast<__half2*>(&g_hG[(size_t)row * 2 * DMODEL + col])       = h0;
                    *reinterpret_cast<__half2*>(&g_hG[(size_t)(row + 8) * 2 * DMODEL + col]) = h1;
                } else {
                    *reinterpret_cast<__half2*>(&g_hG[(size_t)(L_SEQ - 1 - row) * 2 * DMODEL + DMODEL + col]) = h0;
                    *reinterpret_cast<__half2*>(&g_hG[(size_t)(L_SEQ - 9 - row) * 2 * DMODEL + DMODEL + col]) = h1;
                }
            }
        }
    }
}

// ---------------- fp32 -> fp16 conversion (weights + u), grid-stride ----------------
__global__ __launch_bounds__(256) void cvt6_kernel(
    const float* __restrict__ s0, const float* __restrict__ s1,
    const float* __restrict__ s2, const float* __restrict__ s3,
    const float* __restrict__ s4, const float* __restrict__ s5)
{
    const int stride = gridDim.x * blockDim.x;
    const int gid = blockIdx.x * blockDim.x + threadIdx.x;
    const float* srcs[6] = {s0, s1, s2, s3, s4, s5};
    __half* dsts[6] = {g_hWin, g_hWin + DPROJ * DMODEL, g_hWoutF, g_hWoutB, g_hWout, g_hu};
    const int cnts[6] = {DPROJ * DMODEL / 4, DPROJ * DMODEL / 4, DMODEL * DINNER / 4,
                         DMODEL * DINNER / 4, DMODEL * 2 * DMODEL / 4, L_SEQ * DMODEL / 4};
#pragma unroll
    for (int seg = 0; seg < 6; seg++) {
        const float4* src = reinterpret_cast<const float4*>(srcs[seg]);
        uint2* dst = reinterpret_cast<uint2*>(dsts[seg]);
        for (int i = gid; i < cnts[seg]; i += stride)
            dst[i] = f4_to_h4(src[i]);
    }
}

// ---------------- prep: causal dwconv + silu, dt softplus, dA, dtx ----------------
__global__ __launch_bounds__(256) void prep_kernel(
    const float* __restrict__ cw_f, const float* __restrict__ cb_f,
    const float* __restrict__ cw_b, const float* __restrict__ cb_b,
    const float* __restrict__ dtb_f, const float* __restrict__ dtb_b,
    const float* __restrict__ Alog_f, const float* __restrict__ Alog_b)
{
    const int l = blockIdx.x, dir = blockIdx.y, tid = threadIdx.x;
    const float* cw   = dir ? cw_b   : cw_f;
    const float* cb   = dir ? cb_b   : cb_f;
    const float* dtb  = dir ? dtb_b  : dtb_f;
    const float* Alog = dir ? Alog_b : Alog_f;

    const size_t base = (size_t)dir * L_SEQ + l;
    const float* zrow = g_zx + base * DPROJ;

    __shared__ float sdt[NH];
    if (tid < NH) {
        float dt = softplus_f(zrow[4224 + tid] + dtb[tid]);
        sdt[tid] = dt;
        g_dA[base * NH + tid] = expf(-expf(Alog[tid]) * dt);
    }
    __syncthreads();

    for (int c = tid; c < CONVD; c += 256) {
        float s = cb[c];
#pragma unroll
        for (int t = 0; t < 4; t++) {
            int lp = l - 3 + t;
            if (lp >= 0)
                s = fmaf(cw[c * 4 + t],
                         g_zx[((size_t)dir * L_SEQ + lp) * DPROJ + 2048 + c], s);
        }
        float v = silu_f(s);
        if (c < DINNER) {
            g_x[base * DINNER + c]   = v;
            g_dtx[base * DINNER + c] = sdt[c >> 6] * v;
        } else if (c < 2112) {
            g_Bv[base * NST + (c - 2048)] = v;
        } else {
            g_Cv[base * NST + (c - 2112)] = v;
        }
    }
}

// ---------------- pass 1: time-split scan, n-quarter per thread ----------------
// grid (16 = [ns4][ts4], 16 head-pairs, 2 dirs) = 512 blocks, block 128 = 2 heads x 64 p.
// Each thread owns one p and 16 n (one quarter) as 8 f32x2 register pairs.
#define SCH 16

__global__ __launch_bounds__(128) void scan_kernel()
{
    const int bx = blockIdx.x;
    const int ns = bx & 3, ts = bx >> 2;   // ns quarter 0..3, ts chunk 0..3
    const int hg = blockIdx.y, dir = blockIdx.z;
    const int tid = threadIdx.x;
    const int hl = tid >> 6, p = tid & 63;
    const int hh = hg * 2 + hl;

    __shared__ __align__(16) float sB[SCH][16], sC[SCH][16];
    __shared__ __align__(16) float sdt[SCH][128];
    __shared__ float sdA[SCH][2];

    u64t h[8];
#pragma unroll
    for (int j = 0; j < 8; j++) h[j] = 0ull;

    const size_t dbase = (size_t)dir * L_SEQ;
    const int nbase = ns * 16;
    float* yout = (ns == 0) ? g_y : (ns == 1) ? g_y2 : (ns == 2) ? g_y3 : g_y4;

    const int cstart = ts * 256;
    for (int c0 = cstart; c0 < cstart + 256; c0 += SCH) {
        // stage: B/C quarters (16 floats/step), dtx for 2 heads, dA
        {
            if (tid < 64) {
                int s = tid >> 2, f = (tid & 3) << 2;
                *reinterpret_cast<float4*>(&sB[s][f]) =
                    *reinterpret_cast<const float4*>(g_Bv + (dbase + c0 + s) * NST + nbase + f);
            } else {
                int t2 = tid - 64;
                int s = t2 >> 2, f = (t2 & 3) << 2;
                *reinterpret_cast<float4*>(&sC[s][f]) =
                    *reinterpret_cast<const float4*>(g_Cv + (dbase + c0 + s) * NST + nbase + f);
            }
#pragma unroll
            for (int e = 0; e < 4; e++) {
                int idx = tid + e * 128;
                int s2 = idx >> 5, r = idx & 31;
                int h2 = r >> 4, pp = (r & 15) << 2;
                *reinterpret_cast<float4*>(&sdt[s2][h2 * 64 + pp]) =
                    *reinterpret_cast<const float4*>(
                        g_dtx + (dbase + c0 + s2) * DINNER + (hg * 2 + h2) * HD + pp);
            }
            if (tid < SCH * 2)
                sdA[tid >> 1][tid & 1] = g_dA[(dbase + c0 + (tid >> 1)) * NH + hg * 2 + (tid & 1)];
        }
        __syncthreads();

#pragma unroll
        for (int s = 0; s < SCH; s++) {
            const u64t dA2 = pk2(sdA[s][hl]);
            const u64t dt2 = pk2(sdt[s][hl * 64 + p]);
            const ulonglong2* Bp = reinterpret_cast<const ulonglong2*>(&sB[s][0]);
            const ulonglong2* Cq = reinterpret_cast<const ulonglong2*>(&sC[s][0]);
            u64t acc = 0ull;
#pragma unroll
            for (int j = 0; j < 4; j++) {
                ulonglong2 b2 = Bp[j], c2 = Cq[j];
                h[2 * j]     = fma2(h[2 * j],     dA2, mul2(dt2, b2.x));
                acc          = fma2(h[2 * j],     c2.x, acc);
                h[2 * j + 1] = fma2(h[2 * j + 1], dA2, mul2(dt2, b2.y));
                acc          = fma2(h[2 * j + 1], c2.y, acc);
            }
            yout[(dbase + c0 + s) * DINNER + hh * HD + p] = hadd2(acc);
        }
        __syncthreads();
    }

    // store end-of-chunk state at [dir][head][ts] + ps*2048 + nsb*1024 + pl*32 + nl
    {
        size_t stb = ((size_t)((dir * 32 + hh) * 4 + ts)) * 4096
                     + (size_t)(p >> 5) * 2048 + (size_t)(ns >> 1) * 1024
                     + (size_t)(p & 31) * 32 + (size_t)(ns & 1) * 16;
#pragma unroll
        for (int j = 0; j < 4; j++) {
            ulonglong2 st; st.x = h[2 * j]; st.y = h[2 * j + 1];
            *reinterpret_cast<ulonglong2*>(&g_state[stb + j * 4]) = st;
        }
    }
}

// ---------------- pass 2: cumprods + chunk-carry combine (4 chunks of 256) ----------------
__global__ __launch_bounds__(256) void chain_kernel()
{
    const int hh = blockIdx.x, dir = blockIdx.y;
    const int tid = threadIdx.x, lane = tid & 31, warp = tid >> 5;
    const size_t dbase = (size_t)dir * L_SEQ;
    __shared__ float wtot[8];
    __shared__ float scA[4];

    float inc[4];
    float s = 0.f;
#pragma unroll
    for (int j = 0; j < 4; j++) {
        float a = g_dA[(dbase + tid * 4 + j) * NH + hh];
        s += logf(a);
        inc[j] = s;
    }
    const float tot = s;
    float wsc = tot;
#pragma unroll
    for (int off = 1; off < 32; off <<= 1) {
        float v = __shfl_up_sync(0xffffffffu, wsc, off);
        if (lane >= off) wsc += v;
    }
    if (lane == 31) wtot[warp] = wsc;
    __syncthreads();
    float base = (warp & 1) ? wtot[warp - 1] : 0.f;
    float excl = wsc - tot + base;
    const size_t cpb = (size_t)(dir * 32 + hh) * L_SEQ;
#pragma unroll
    for (int j = 0; j < 4; j++)
        g_cp[cpb + tid * 4 + j] = expf(excl + inc[j]);
    if ((tid & 63) == 63) scA[tid >> 6] = expf(excl + tot);
    __syncthreads();

    const size_t sb = (size_t)(dir * 32 + hh) * 4 * 4096;
    const size_t cb = (size_t)(dir * 32 + hh) * 3 * 4096;
    const float A1 = scA[1], A2 = scA[2];
    for (int e = 0; e < 16; e++) {
        int idx = tid + e * 256;
        float c1 = g_state[sb + idx];
        float c2 = g_state[sb + 4096 + idx] + A1 * c1;
        float c3 = g_state[sb + 2 * 4096 + idx] + A2 * c2;
        g_carry[cb + idx]            = c1;
        g_carry[cb + 4096 + idx]     = c2;
        g_carry[cb + 2 * 4096 + idx] = c3;
    }
}

// ---------------- pass 3: correction y[t] += cp[t] * (C[t] . carry) ----------------
// grid (12 tiles = [chunk 1..3][4 t-subtiles of 64], 32 heads, 2 dirs), block 256.
__global__ __launch_bounds__(256) void corr_kernel()
{
    const int tile = blockIdx.x;
    const int hh = blockIdx.y, dir = blockIdx.z;
    const int chunk = 1 + (tile >> 2);
    const int t0 = chunk * 256 + (tile & 3) * 64;
    const int tid = threadIdx.x;
    const size_t dbase = (size_t)dir * L_SEQ;

    __shared__ float sC[64 * 65];
    __shared__ __align__(16) float sCar[64 * 68];
    __shared__ float scp[64];

    const size_t cb = (size_t)(dir * 32 + hh) * 3 * 4096 + (size_t)(chunk - 1) * 4096;
#pragma unroll
    for (int e = 0; e < 16; e++) {
        int idx = tid + e * 256;
        int ps = idx >> 11, nsb = (idx >> 10) & 1, pl = (idx >> 5) & 31, nl = idx & 31;
        sCar[(nsb * 32 + nl) * 68 + ps * 32 + pl] = g_carry[cb + idx];
    }
#pragma unroll
    for (int e = 0; e < 4; e++) {
        int f = tid + e * 256;
        int tl = f >> 4, nq = (f & 15) * 4;
        float4 v = *reinterpret_cast<const float4*>(g_Cv + (dbase + t0 + tl) * NST + nq);
        sC[tl * 65 + nq]     = v.x; sC[tl * 65 + nq + 1] = v.y;
        sC[tl * 65 + nq + 2] = v.z; sC[tl * 65 + nq + 3] = v.w;
    }
    if (tid < 64) scp[tid] = g_cp[(size_t)(dir * 32 + hh) * L_SEQ + t0 + tid];
    __syncthreads();

    const int tq = tid >> 4, pq = tid & 15;
    u64t acc[4][2];
#pragma unroll
    for (int i = 0; i < 4; i++) { acc[i][0] = 0ull; acc[i][1] = 0ull; }

#pragma unroll 4
    for (int n = 0; n < 64; n++) {
        ulonglong2 car = *reinterpret_cast<const ulonglong2*>(&sCar[n * 68 + pq * 4]);
#pragma unroll
        for (int j = 0; j < 4; j++) {
            u64t cv = pk2(sC[(tq * 4 + j) * 65 + n]);
            acc[j][0] = fma2(cv, car.x, acc[j][0]);
            acc[j][1] = fma2(cv, car.y, acc[j][1]);
        }
    }

#pragma unroll
    for (int j = 0; j < 4; j++) {
        int t = t0 + tq * 4 + j;
        float cp = scp[tq * 4 + j];
        float a0, a1, a2, a3;
        asm("mov.b64 {%0,%1}, %2;" : "=f"(a0), "=f"(a1) : "l"(acc[j][0]));
        asm("mov.b64 {%0,%1}, %2;" : "=f"(a2), "=f"(a3) : "l"(acc[j][1]));
        float4* yp = reinterpret_cast<float4*>(g_y + (dbase + t) * DINNER + hh * 64 + pq * 4);
        float4 v = *yp;
        v.x += cp * a0; v.y += cp * a1; v.z += cp * a2; v.w += cp * a3;
        *yp = v;
    }
}

// ---------------- gate: (y0..y3) + D*x, *silu(z), rmsnorm, *norm_w -> fp16 ----------------
__global__ __launch_bounds__(256) void gate_kernel(
    const float* __restrict__ D_f, const float* __restrict__ D_b,
    const float* __restrict__ nw_f, const float* __restrict__ nw_b)
{
    const int l = blockIdx.x, dir = blockIdx.y, tid = threadIdx.x;
    const float* Dp = dir ? D_b : D_f;
    const float* nw = dir ? nw_b : nw_f;
    const size_t base = (size_t)dir * L_SEQ + l;

    const float4* y4a = reinterpret_cast<const float4*>(g_y  + base * DINNER);
    const float4* y4b = reinterpret_cast<const float4*>(g_y2 + base * DINNER);
    const float4* y4c = reinterpret_cast<const float4*>(g_y3 + base * DINNER);
    const float4* y4d = reinterpret_cast<const float4*>(g_y4 + base * DINNER);
    const float4* x4  = reinterpret_cast<const float4*>(g_x  + base * DINNER);
    const float4* z4  = reinterpret_cast<const float4*>(g_zx + base * DPROJ);
    float4* o4 = reinterpret_cast<float4*>(g_ygn + base * DINNER);
    uint2* h4 = reinterpret_cast<uint2*>(g_hygn + base * DINNER);

    float ss = 0.f;
#pragma unroll
    for (int it = 0; it < 2; it++) {
        int c4 = tid + it * 256;
        float dd = Dp[c4 >> 4];
        float4 a = y4a[c4], b = y4b[c4], c = y4c[c4], d = y4d[c4];
        float4 x = x4[c4], z = z4[c4];
        float4 r;
        r.x = (a.x + b.x + c.x + d.x + dd * x.x) * silu_f(z.x);
        r.y = (a.y + b.y + c.y + d.y + dd * x.y) * silu_f(z.y);
        r.z = (a.z + b.z + c.z + d.z + dd * x.z) * silu_f(z.z);
        r.w = (a.w + b.w + c.w + d.w + dd * x.w) * silu_f(z.w);
        o4[c4] = r;
        ss += r.x * r.x + r.y * r.y + r.z * r.z + r.w * r.w;
    }
    __shared__ float red[8];
#pragma unroll
    for (int o = 16; o; o >>= 1) ss += __shfl_xor_sync(0xffffffffu, ss, o);
    if ((tid & 31) == 0) red[tid >> 5] = ss;
    __syncthreads();
    if (tid < 8) {
        float v = red[tid];
#pragma unroll
        for (int o = 4; o; o >>= 1) v += __shfl_xor_sync(0xffu, v, o);
        if (tid == 0) red[0] = v;
    }
    __syncthreads();
    const float scale = rsqrtf(red[0] * (1.f / DINNER) + 1e-5f);
    const float4* nw4 = reinterpret_cast<const float4*>(nw);
#pragma unroll
    for (int it = 0; it < 2; it++) {
        int c4 = tid + it * 256;
        float4 r = o4[c4], w = nw4[c4];
        r.x *= scale * w.x; r.y *= scale * w.y; r.z *= scale * w.z; r.w *= scale * w.w;
        h4[c4] = f4_to_h4(r);
    }
}

// ---------------- launch ----------------
extern "C" void kernel_launch(void* const* d_in, const int* in_sizes, int n_in,
                              void* d_out, int out_size)
{
    const float* u         = (const float*)d_in[0];
    const float* W_in_f    = (const float*)d_in[1];
    const float* W_in_b    = (const float*)d_in[2];
    const float* conv_w_f  = (const float*)d_in[3];
    const float* conv_b_f  = (const float*)d_in[4];
    const float* conv_w_b  = (const float*)d_in[5];
    const float* conv_b_b  = (const float*)d_in[6];
    const float* dt_bias_f = (const float*)d_in[7];
    const float* dt_bias_b = (const float*)d_in[8];
    const float* A_log_f   = (const float*)d_in[9];
    const float* A_log_b   = (const float*)d_in[10];
    const float* D_f       = (const float*)d_in[11];
    const float* D_b       = (const float*)d_in[12];
    const float* norm_w_f  = (const float*)d_in[13];
    const float* norm_w_b  = (const float*)d_in[14];
    const float* W_out_f   = (const float*)d_in[15];
    const float* W_out_b   = (const float*)d_in[16];
    const float* W_out     = (const float*)d_in[17];

    static int attr_done = 0;
    if (!attr_done) {
        cudaFuncSetAttribute(gemm_hp, cudaFuncAttributeMaxDynamicSharedMemorySize, GEMM_SMEM);
        attr_done = 1;
    }

    float *zx;
    __half *hWin, *hWoutF, *hWoutB, *hWout, *hu, *hygn, *hG;
    cudaGetSymbolAddress((void**)&zx,     g_zx);
    cudaGetSymbolAddress((void**)&hWin,   g_hWin);
    cudaGetSymbolAddress((void**)&hWoutF, g_hWoutF);
    cudaGetSymbolAddress((void**)&hWoutB, g_hWoutB);
    cudaGetSymbolAddress((void**)&hWout,  g_hWout);
    cudaGetSymbolAddress((void**)&hu,     g_hu);
    cudaGetSymbolAddress((void**)&hygn,   g_hygn);
    cudaGetSymbolAddress((void**)&hG,     g_hG);

    // 0) fp32 -> fp16 conversions (weights + u)
    cvt6_kernel<<<1024, 256>>>(W_in_f, W_in_b, W_out_f, W_out_b, W_out, u);

    // 1) in_proj, both directions (z=dir; flip A rows when z==1)
    gemm_hp<<<dim3((DPROJ + 127) / 128, L_SEQ / 128, 2), 256, GEMM_SMEM>>>(
        hu, DMODEL, 1, hWin, hWin + (size_t)DPROJ * DMODEL, DMODEL, zx, DPROJ,
        L_SEQ, DPROJ, DMODEL, 0, (long)L_SEQ * DPROJ, 0);

    // 2) conv + silu + dt/dA/dtx
    prep_kernel<<<dim3(L_SEQ, 2), 256>>>(conv_w_f, conv_b_f, conv_w_b, conv_b_b,
                                         dt_bias_f, dt_bias_b, A_log_f, A_log_b);

    // 3) time-split scan: local chunks (n-quarter per thread), carry chain, correction
    scan_kernel<<<dim3(16, 16, 2), 128>>>();
    chain_kernel<<<dim3(NH, 2), 256>>>();
    corr_kernel<<<dim3(12, NH, 2), 256>>>();

    // 4) gate + rmsnorm -> fp16 ygn
    gate_kernel<<<dim3(L_SEQ, 2), 256>>>(D_f, D_b, norm_w_f, norm_w_b);

    // 5) out projections, epi=1 fuses silu + concat + flip into g_hG
    gemm_hp<<<dim3(DMODEL / 128, L_SEQ / 128, 2), 256, GEMM_SMEM>>>(
        hygn, DINNER, 0, hWoutF, hWoutB, DINNER, zx /*unused*/, DMODEL,
        L_SEQ, DMODEL, DINNER, (long)L_SEQ * DINNER, 0, 1);

    // 6) final projection
    gemm_hp<<<dim3(DMODEL / 128, L_SEQ / 128, 1), 256, GEMM_SMEM>>>(
        hG, 2 * DMODEL, 0, hWout, hWout, 2 * DMODEL, (float*)d_out, DMODEL,
        L_SEQ, DMODEL, 2 * DMODEL, 0, 0, 0);
}

// round 16
// speedup vs baseline: 1.1162x; 1.0322x over previous
#include <cuda_runtime.h>
#include <cuda_fp16.h>
#include <cstdint>

#define L_SEQ  1024
#define DMODEL 1024
#define DINNER 2048
#define NH     32
#define HD     64
#define NST    64
#define CONVD  2176
#define DPROJ  4256

// ---------------- scratch (static device globals; no allocations) ----------------
__device__ __align__(128) float g_zx [2 * L_SEQ * DPROJ];
__device__ __align__(128) float g_x  [2 * L_SEQ * DINNER];
__device__ __align__(128) float g_dtx[2 * L_SEQ * DINNER];
__device__ __align__(128) float g_dA [2 * L_SEQ * NH];
__device__ __align__(128) float g_Bv [2 * L_SEQ * NST];
__device__ __align__(128) float g_Cv [2 * L_SEQ * NST];
__device__ __align__(128) float g_y  [2 * L_SEQ * DINNER];   // n-quarter 0 partial (+corr)
__device__ __align__(128) float g_y2 [2 * L_SEQ * DINNER];   // n-quarter 1 partial
__device__ __align__(128) float g_y3 [2 * L_SEQ * DINNER];   // n-quarter 2 partial
__device__ __align__(128) float g_y4 [2 * L_SEQ * DINNER];   // n-quarter 3 partial
__device__ __align__(128) float g_ygn[2 * L_SEQ * DINNER];   // fp32 scratch (pre-norm)

// time-split scan scratch (4 chunks of 256)
__device__ __align__(128) float g_state[2 * 32 * 4 * 4096];  // [dir][head][ts][ps][nsb][pl][n32]
__device__ __align__(128) float g_carry[2 * 32 * 3 * 4096];  // carry-in for chunks 1..3
__device__ __align__(128) float g_cp   [2 * 32 * L_SEQ];     // within-chunk cumprod of dA

// fp16 mirrors for GEMM inputs
__device__ __align__(128) __half g_hWin  [2 * DPROJ * DMODEL];
__device__ __align__(128) __half g_hWoutF[DMODEL * DINNER];
__device__ __align__(128) __half g_hWoutB[DMODEL * DINNER];
__device__ __align__(128) __half g_hWout [DMODEL * 2 * DMODEL];
__device__ __align__(128) __half g_hu    [L_SEQ * DMODEL];
__device__ __align__(128) __half g_hygn  [2 * L_SEQ * DINNER];
__device__ __align__(128) __half g_hG    [L_SEQ * 2 * DMODEL];

// ---------------- helpers ----------------
__device__ __forceinline__ float silu_f(float v) { return v / (1.f + expf(-v)); }
__device__ __forceinline__ float softplus_f(float v) { return v > 20.f ? v : log1pf(expf(v)); }

// packed fp32x2 ops (sm_103a FFMA2 path — PTX-only)
typedef unsigned long long u64t;
__device__ __forceinline__ u64t pk2(float v) {
    u64t r; asm("mov.b64 %0, {%1, %1};" : "=l"(r) : "f"(v)); return r;
}
__device__ __forceinline__ u64t fma2(u64t a, u64t b, u64t c) {
    u64t d; asm("fma.rn.f32x2 %0, %1, %2, %3;" : "=l"(d) : "l"(a), "l"(b), "l"(c)); return d;
}
__device__ __forceinline__ u64t mul2(u64t a, u64t b) {
    u64t d; asm("mul.rn.f32x2 %0, %1, %2;" : "=l"(d) : "l"(a), "l"(b)); return d;
}
__device__ __forceinline__ float hadd2(u64t a) {
    float lo, hi; asm("mov.b64 {%0, %1}, %2;" : "=f"(lo), "=f"(hi) : "l"(a)); return lo + hi;
}

__device__ __forceinline__ void mma_f16(float* c, const uint32_t* a, uint32_t b0, uint32_t b1) {
    asm volatile(
        "mma.sync.aligned.m16n8k16.row.col.f32.f16.f16.f32 "
        "{%0,%1,%2,%3},{%4,%5,%6,%7},{%8,%9},{%0,%1,%2,%3};"
        : "+f"(c[0]), "+f"(c[1]), "+f"(c[2]), "+f"(c[3])
        : "r"(a[0]), "r"(a[1]), "r"(a[2]), "r"(a[3]), "r"(b0), "r"(b1));
}

__device__ __forceinline__ uint2 f4_to_h4(float4 v) {
    __half2 lo = __floats2half2_rn(v.x, v.y);
    __half2 hi = __floats2half2_rn(v.z, v.w);
    uint2 r;
    r.x = *reinterpret_cast<uint32_t*>(&lo);
    r.y = *reinterpret_cast<uint32_t*>(&hi);
    return r;
}

__device__ __forceinline__ uint32_t smem_u32(const void* p) {
    uint32_t a;
    asm("{ .reg .u64 t; cvta.to.shared.u64 t, %1; cvt.u32.u64 %0, t; }" : "=r"(a) : "l"(p));
    return a;
}
__device__ __forceinline__ uint32_t swz64(uint32_t o) { return o ^ ((o >> 3) & 0x30); }

#define CP16(dst, src) \
    asm volatile("cp.async.cg.shared.global [%0], [%1], 16;" :: "r"(dst), "l"(src) : "memory")
#define CP4(dst, src) \
    asm volatile("cp.async.ca.shared.global [%0], [%1], 4;" :: "r"(dst), "l"(src) : "memory")
#define CP_COMMIT() asm volatile("cp.async.commit_group;" ::: "memory")
#define CP_WAIT0()  asm volatile("cp.async.wait_group 0;" ::: "memory")
#define CP_WAIT1()  asm volatile("cp.async.wait_group 1;" ::: "memory")
#define CP_WAIT2()  asm volatile("cp.async.wait_group 2;" ::: "memory")

#define LDSM4(r, addr) \
    asm volatile("ldmatrix.sync.aligned.m8n8.x4.shared.b16 {%0,%1,%2,%3}, [%4];" \
                 : "=r"((r)[0]), "=r"((r)[1]), "=r"((r)[2]), "=r"((r)[3]) : "r"(addr))

// ---------------- fp16 GEMM, 4-stage cp.async + ldmatrix ----------------
#define STG_BYTES 16384
#define GEMM_SMEM (4 * STG_BYTES)

__global__ __launch_bounds__(256, 2) void gemm_hp(
    const __half* __restrict__ A, int lda, int flip_z1,
    const __half* __restrict__ W0, const __half* __restrict__ W1, int ldw,
    float* __restrict__ C, int ldc, int M, int N, int K,
    long strideA, long strideC, int epi)
{
    extern __shared__ __align__(128) char smem[];
    const uint32_t sbase = smem_u32(smem);

    const int z = blockIdx.z;
    const __half* Ap = A + (size_t)z * strideA;
    const __half* W  = z ? W1 : W0;
    float* Cp = C + (size_t)z * strideC;
    const bool flipA = (flip_z1 && z == 1);

    const int tid  = threadIdx.x;
    const int warp = tid >> 5, lane = tid & 31;
    const int g = lane >> 2, tg = lane & 3;
    const int wm = warp >> 2, wn = warp & 3;
    const int mblk = blockIdx.y * 128;
    const int nblk = blockIdx.x * 128;
    const int m0 = wm * 64, n0 = wn * 32;

    uint32_t offA[4][2], offB[2][2];
    {
        int mrow = (lane & 7) + ((lane >> 3) & 1) * 8;
        int kcA  = lane >> 4;
#pragma unroll
        for (int mt = 0; mt < 4; mt++)
#pragma unroll
            for (int ks = 0; ks < 2; ks++)
                offA[mt][ks] = swz64((m0 + mt * 16 + mrow) * 64 + ks * 32 + kcA * 16);
        int nrow = (lane & 7) + (lane >> 4) * 8;
        int kcB  = (lane >> 3) & 1;
#pragma unroll
        for (int p = 0; p < 2; p++)
#pragma unroll
            for (int ks = 0; ks < 2; ks++)
                offB[p][ks] = swz64((n0 + p * 16 + nrow) * 64 + ks * 32 + kcB * 16) + 8192;
    }

    const int srow0 = tid >> 2,          spos0 = tid & 3;
    const int srow1 = (tid + 256) >> 2,  spos1 = (tid + 256) & 3;
    const uint32_t sd0 = swz64(srow0 * 64 + spos0 * 16);
    const uint32_t sd1 = swz64(srow1 * 64 + spos1 * 16);

    const int T = K / 32;

#define ISSUE(t_) do {                                                         \
        int kt = (t_) * 32;                                                    \
        uint32_t sb = sbase + ((t_) & 3) * STG_BYTES;                          \
        {   int gr = mblk + srow0; int rA = flipA ? (M - 1 - gr) : gr;         \
            CP16(sb + sd0, Ap + (size_t)rA * lda + kt + spos0 * 8);            \
            int gn = nblk + srow0; if (gn >= N) gn = N - 1;                    \
            CP16(sb + 8192 + sd0, W + (size_t)gn * ldw + kt + spos0 * 8); }    \
        {   int gr = mblk + srow1; int rA = flipA ? (M - 1 - gr) : gr;         \
            CP16(sb + sd1, Ap + (size_t)rA * lda + kt + spos1 * 8);            \
            int gn = nblk + srow1; if (gn >= N) gn = N - 1;                    \
            CP16(sb + 8192 + sd1, W + (size_t)gn * ldw + kt + spos1 * 8); }    \
    } while (0)

    ISSUE(0); CP_COMMIT();
    ISSUE(1); CP_COMMIT();
    ISSUE(2); CP_COMMIT();

    float acc[4][4][4];
#pragma unroll
    for (int i = 0; i < 4; i++)
#pragma unroll
        for (int j = 0; j < 4; j++)
#pragma unroll
            for (int r = 0; r < 4; r++) acc[i][j][r] = 0.f;

    for (int t = 0; t < T; t++) {
        CP_WAIT2();
        __syncthreads();
        const uint32_t sb = sbase + (t & 3) * STG_BYTES;

#pragma unroll
        for (int ks = 0; ks < 2; ks++) {
            uint32_t a[4][4], b[2][4];
#pragma unroll
            for (int mt = 0; mt < 4; mt++) LDSM4(a[mt], sb + offA[mt][ks]);
#pragma unroll
            for (int p = 0; p < 2; p++)    LDSM4(b[p], sb + offB[p][ks]);
#pragma unroll
            for (int mt = 0; mt < 4; mt++)
#pragma unroll
                for (int nt = 0; nt < 4; nt++)
                    mma_f16(acc[mt][nt], a[mt], b[nt >> 1][(nt & 1) * 2],
                            b[nt >> 1][(nt & 1) * 2 + 1]);
        }

        if (t + 3 < T) ISSUE(t + 3);
        CP_COMMIT();
    }

    if (epi == 0) {
#pragma unroll
        for (int mt = 0; mt < 4; mt++) {
#pragma unroll
            for (int nt = 0; nt < 4; nt++) {
                int row = mblk + m0 + mt * 16 + g;
                int col = nblk + n0 + nt * 8 + 2 * tg;
                if (col < N) {
                    Cp[(size_t)row * ldc + col]           = acc[mt][nt][0];
                    Cp[(size_t)(row + 8) * ldc + col]     = acc[mt][nt][2];
                }
                if (col + 1 < N) {
                    Cp[(size_t)row * ldc + col + 1]       = acc[mt][nt][1];
                    Cp[(size_t)(row + 8) * ldc + col + 1] = acc[mt][nt][3];
                }
            }
        }
    } else {
#pragma unroll
        for (int mt = 0; mt < 4; mt++) {
#pragma unroll
            for (int nt = 0; nt < 4; nt++) {
                int row = mblk + m0 + mt * 16 + g;
                int col = nblk + n0 + nt * 8 + 2 * tg;
                __half2 h0 = __floats2half2_rn(silu_f(acc[mt][nt][0]), silu_f(acc[mt][nt][1]));
                __half2 h1 = __floats2half2_rn(silu_f(acc[mt][nt][2]), silu_f(acc[mt][nt][3]));
                if (z == 0) {
                    *reinterpret_cast<__half2*>(&g_hG[(size_t)row * 2 * DMODEL + col])       = h0;
                    *reinterpret_cast<__half2*>(&g_hG[(size_t)(row + 8) * 2 * DMODEL + col]) = h1;
                } else {
                    *reinterpret_cast<__half2*>(&g_hG[(size_t)(L_SEQ - 1 - row) * 2 * DMODEL + DMODEL + col]) = h0;
                    *reinterpret_cast<__half2*>(&g_hG[(size_t)(L_SEQ - 9 - row) * 2 * DMODEL + DMODEL + col]) = h1;
                }
            }
        }
    }
}

// ---------------- fp32 -> fp16 conversion (weights + u), grid-stride ----------------
__global__ __launch_bounds__(256) void cvt6_kernel(
    const float* __restrict__ s0, const float* __restrict__ s1,
    const float* __restrict__ s2, const float* __restrict__ s3,
    const float* __restrict__ s4, const float* __restrict__ s5)
{
    const int stride = gridDim.x * blockDim.x;
    const int gid = blockIdx.x * blockDim.x + threadIdx.x;
    const float* srcs[6] = {s0, s1, s2, s3, s4, s5};
    __half* dsts[6] = {g_hWin, g_hWin + DPROJ * DMODEL, g_hWoutF, g_hWoutB, g_hWout, g_hu};
    const int cnts[6] = {DPROJ * DMODEL / 4, DPROJ * DMODEL / 4, DMODEL * DINNER / 4,
                         DMODEL * DINNER / 4, DMODEL * 2 * DMODEL / 4, L_SEQ * DMODEL / 4};
#pragma unroll
    for (int seg = 0; seg < 6; seg++) {
        const float4* src = reinterpret_cast<const float4*>(srcs[seg]);
        uint2* dst = reinterpret_cast<uint2*>(dsts[seg]);
        for (int i = gid; i < cnts[seg]; i += stride)
            dst[i] = f4_to_h4(src[i]);
    }
}

// ---------------- prep: causal dwconv + silu, dt softplus, dA, dtx ----------------
__global__ __launch_bounds__(256) void prep_kernel(
    const float* __restrict__ cw_f, const float* __restrict__ cb_f,
    const float* __restrict__ cw_b, const float* __restrict__ cb_b,
    const float* __restrict__ dtb_f, const float* __restrict__ dtb_b,
    const float* __restrict__ Alog_f, const float* __restrict__ Alog_b)
{
    const int l = blockIdx.x, dir = blockIdx.y, tid = threadIdx.x;
    const float* cw   = dir ? cw_b   : cw_f;
    const float* cb   = dir ? cb_b   : cb_f;
    const float* dtb  = dir ? dtb_b  : dtb_f;
    const float* Alog = dir ? Alog_b : Alog_f;

    const size_t base = (size_t)dir * L_SEQ + l;
    const float* zrow = g_zx + base * DPROJ;

    __shared__ float sdt[NH];
    if (tid < NH) {
        float dt = softplus_f(zrow[4224 + tid] + dtb[tid]);
        sdt[tid] = dt;
        g_dA[base * NH + tid] = expf(-expf(Alog[tid]) * dt);
    }
    __syncthreads();

    for (int c = tid; c < CONVD; c += 256) {
        float s = cb[c];
#pragma unroll
        for (int t = 0; t < 4; t++) {
            int lp = l - 3 + t;
            if (lp >= 0)
                s = fmaf(cw[c * 4 + t],
                         g_zx[((size_t)dir * L_SEQ + lp) * DPROJ + 2048 + c], s);
        }
        float v = silu_f(s);
        if (c < DINNER) {
            g_x[base * DINNER + c]   = v;
            g_dtx[base * DINNER + c] = sdt[c >> 6] * v;
        } else if (c < 2112) {
            g_Bv[base * NST + (c - 2048)] = v;
        } else {
            g_Cv[base * NST + (c - 2112)] = v;
        }
    }
}

// ---------------- pass 1: time-split scan, 64-thread blocks + cp.async staging -------
// grid (16 = [ns4][ts4], 32 heads, 2 dirs) = 1024 blocks, block 64 = 1 head x 64 p.
// Each thread owns one p and 16 n (one quarter) as 8 f32x2 register pairs.
// Double-buffered cp.async staging hides gmem latency; B/C LDS are warp broadcasts.
#define SCH 16

__global__ __launch_bounds__(64) void scan_kernel()
{
    const int bx = blockIdx.x;
    const int ns = bx & 3, ts = bx >> 2;   // ns quarter 0..3, ts chunk 0..3
    const int hh = blockIdx.y, dir = blockIdx.z;
    const int tid = threadIdx.x;           // = p (0..63)

    __shared__ __align__(16) float sB[2][SCH][16], sC[2][SCH][16];
    __shared__ __align__(16) float sdt[2][SCH][64];
    __shared__ float sdA[2][SCH];

    const uint32_t uB  = smem_u32(sB);
    const uint32_t uC  = smem_u32(sC);
    const uint32_t uDT = smem_u32(sdt);
    const uint32_t uDA = smem_u32(sdA);

    u64t h[8];
#pragma unroll
    for (int j = 0; j < 8; j++) h[j] = 0ull;

    const size_t dbase = (size_t)dir * L_SEQ;
    const int nbase = ns * 16;
    float* yout = (ns == 0) ? g_y : (ns == 1) ? g_y2 : (ns == 2) ? g_y3 : g_y4;
    const int cstart = ts * 256;

    // staging coordinates
    const int sb_s = tid >> 2, sb_f = (tid & 3) << 2;   // B/C: 1 float4 each

#define SCAN_ISSUE(k_) do {                                                          \
        const int c0_ = cstart + (k_) * SCH;                                         \
        const uint32_t bb_ = ((k_) & 1);                                             \
        CP16(uB + bb_ * 1024 + sb_s * 64 + sb_f * 4,                                 \
             g_Bv + (dbase + c0_ + sb_s) * NST + nbase + sb_f);                      \
        CP16(uC + bb_ * 1024 + sb_s * 64 + sb_f * 4,                                 \
             g_Cv + (dbase + c0_ + sb_s) * NST + nbase + sb_f);                      \
        _Pragma("unroll")                                                            \
        for (int e = 0; e < 4; e++) {                                                \
            int idx = tid + e * 64;                                                  \
            int s2 = idx >> 4, pp = (idx & 15) << 2;                                 \
            CP16(uDT + bb_ * 4096 + s2 * 256 + pp * 4,                               \
                 g_dtx + (dbase + c0_ + s2) * DINNER + hh * HD + pp);                \
        }                                                                            \
        if (tid < SCH)                                                               \
            CP4(uDA + bb_ * 64 + tid * 4, g_dA + (dbase + c0_ + tid) * NH + hh);     \
    } while (0)

    SCAN_ISSUE(0); CP_COMMIT();

    for (int k = 0; k < 16; k++) {
        if (k < 15) { SCAN_ISSUE(k + 1); CP_COMMIT(); CP_WAIT1(); }
        else        { CP_WAIT0(); }
        __syncthreads();

        const int b = k & 1;
        const int c0 = cstart + k * SCH;
#pragma unroll
        for (int s = 0; s < SCH; s++) {
            const u64t dA2 = pk2(sdA[b][s]);
            const u64t dt2 = pk2(sdt[b][s][tid]);
            const ulonglong2* Bp = reinterpret_cast<const ulonglong2*>(&sB[b][s][0]);
            const ulonglong2* Cq = reinterpret_cast<const ulonglong2*>(&sC[b][s][0]);
            u64t acc = 0ull;
#pragma unroll
            for (int j = 0; j < 4; j++) {
                ulonglong2 b2 = Bp[j], c2 = Cq[j];
                h[2 * j]     = fma2(h[2 * j],     dA2, mul2(dt2, b2.x));
                acc          = fma2(h[2 * j],     c2.x, acc);
                h[2 * j + 1] = fma2(h[2 * j + 1], dA2, mul2(dt2, b2.y));
                acc          = fma2(h[2 * j + 1], c2.y, acc);
            }
            yout[(dbase + c0 + s) * DINNER + hh * HD + tid] = hadd2(acc);
        }
        __syncthreads();
    }

    // store end-of-chunk state at [dir][head][ts] + ps*2048 + nsb*1024 + pl*32 + nl
    {
        size_t stb = ((size_t)((dir * 32 + hh) * 4 + ts)) * 4096
                     + (size_t)(tid >> 5) * 2048 + (size_t)(ns >> 1) * 1024
                     + (size_t)(tid & 31) * 32 + (size_t)(ns & 1) * 16;
#pragma unroll
        for (int j = 0; j < 4; j++) {
            ulonglong2 st; st.x = h[2 * j]; st.y = h[2 * j + 1];
            *reinterpret_cast<ulonglong2*>(&g_state[stb + j * 4]) = st;
        }
    }
}

// ---------------- pass 2: cumprods + chunk-carry combine (4 chunks of 256) ----------------
__global__ __launch_bounds__(256) void chain_kernel()
{
    const int hh = blockIdx.x, dir = blockIdx.y;
    const int tid = threadIdx.x, lane = tid & 31, warp = tid >> 5;
    const size_t dbase = (size_t)dir * L_SEQ;
    __shared__ float wtot[8];
    __shared__ float scA[4];

    float inc[4];
    float s = 0.f;
#pragma unroll
    for (int j = 0; j < 4; j++) {
        float a = g_dA[(dbase + tid * 4 + j) * NH + hh];
        s += logf(a);
        inc[j] = s;
    }
    const float tot = s;
    float wsc = tot;
#pragma unroll
    for (int off = 1; off < 32; off <<= 1) {
        float v = __shfl_up_sync(0xffffffffu, wsc, off);
        if (lane >= off) wsc += v;
    }
    if (lane == 31) wtot[warp] = wsc;
    __syncthreads();
    float base = (warp & 1) ? wtot[warp - 1] : 0.f;
    float excl = wsc - tot + base;
    const size_t cpb = (size_t)(dir * 32 + hh) * L_SEQ;
#pragma unroll
    for (int j = 0; j < 4; j++)
        g_cp[cpb + tid * 4 + j] = expf(excl + inc[j]);
    if ((tid & 63) == 63) scA[tid >> 6] = expf(excl + tot);
    __syncthreads();

    const size_t sb = (size_t)(dir * 32 + hh) * 4 * 4096;
    const size_t cb = (size_t)(dir * 32 + hh) * 3 * 4096;
    const float A1 = scA[1], A2 = scA[2];
    for (int e = 0; e < 16; e++) {
        int idx = tid + e * 256;
        float c1 = g_state[sb + idx];
        float c2 = g_state[sb + 4096 + idx] + A1 * c1;
        float c3 = g_state[sb + 2 * 4096 + idx] + A2 * c2;
        g_carry[cb + idx]            = c1;
        g_carry[cb + 4096 + idx]     = c2;
        g_carry[cb + 2 * 4096 + idx] = c3;
    }
}

// ---------------- pass 3: correction y[t] += cp[t] * (C[t] . carry) ----------------
// grid (12 tiles = [chunk 1..3][4 t-subtiles of 64], 32 heads, 2 dirs), block 256.
__global__ __launch_bounds__(256) void corr_kernel()
{
    const int tile = blockIdx.x;
    const int hh = blockIdx.y, dir = blockIdx.z;
    const int chunk = 1 + (tile >> 2);
    const int t0 = chunk * 256 + (tile & 3) * 64;
    const int tid = threadIdx.x;
    const size_t dbase = (size_t)dir * L_SEQ;

    __shared__ float sC[64 * 65];
    __shared__ __align__(16) float sCar[64 * 68];
    __shared__ float scp[64];

    const size_t cb = (size_t)(dir * 32 + hh) * 3 * 4096 + (size_t)(chunk - 1) * 4096;
#pragma unroll
    for (int e = 0; e < 16; e++) {
        int idx = tid + e * 256;
        int ps = idx >> 11, nsb = (idx >> 10) & 1, pl = (idx >> 5) & 31, nl = idx & 31;
        sCar[(nsb * 32 + nl) * 68 + ps * 32 + pl] = g_carry[cb + idx];
    }
#pragma unroll
    for (int e = 0; e < 4; e++) {
        int f = tid + e * 256;
        int tl = f >> 4, nq = (f & 15) * 4;
        float4 v = *reinterpret_cast<const float4*>(g_Cv + (dbase + t0 + tl) * NST + nq);
        sC[tl * 65 + nq]     = v.x; sC[tl * 65 + nq + 1] = v.y;
        sC[tl * 65 + nq + 2] = v.z; sC[tl * 65 + nq + 3] = v.w;
    }
    if (tid < 64) scp[tid] = g_cp[(size_t)(dir * 32 + hh) * L_SEQ + t0 + tid];
    __syncthreads();

    const int tq = tid >> 4, pq = tid & 15;
    u64t acc[4][2];
#pragma unroll
    for (int i = 0; i < 4; i++) { acc[i][0] = 0ull; acc[i][1] = 0ull; }

#pragma unroll 4
    for (int n = 0; n < 64; n++) {
        ulonglong2 car = *reinterpret_cast<const ulonglong2*>(&sCar[n * 68 + pq * 4]);
#pragma unroll
        for (int j = 0; j < 4; j++) {
            u64t cv = pk2(sC[(tq * 4 + j) * 65 + n]);
            acc[j][0] = fma2(cv, car.x, acc[j][0]);
            acc[j][1] = fma2(cv, car.y, acc[j][1]);
        }
    }

#pragma unroll
    for (int j = 0; j < 4; j++) {
        int t = t0 + tq * 4 + j;
        float cp = scp[tq * 4 + j];
        float a0, a1, a2, a3;
        asm("mov.b64 {%0,%1}, %2;" : "=f"(a0), "=f"(a1) : "l"(acc[j][0]));
        asm("mov.b64 {%0,%1}, %2;" : "=f"(a2), "=f"(a3) : "l"(acc[j][1]));
        float4* yp = reinterpret_cast<float4*>(g_y + (dbase + t) * DINNER + hh * 64 + pq * 4);
        float4 v = *yp;
        v.x += cp * a0; v.y += cp * a1; v.z += cp * a2; v.w += cp * a3;
        *yp = v;
    }
}

// ---------------- gate: (y0..y3) + D*x, *silu(z), rmsnorm, *norm_w -> fp16 ----------------
__global__ __launch_bounds__(256) void gate_kernel(
    const float* __restrict__ D_f, const float* __restrict__ D_b,
    const float* __restrict__ nw_f, const float* __restrict__ nw_b)
{
    const int l = blockIdx.x, dir = blockIdx.y, tid = threadIdx.x;
    const float* Dp = dir ? D_b : D_f;
    const float* nw = dir ? nw_b : nw_f;
    const size_t base = (size_t)dir * L_SEQ + l;

    const float4* y4a = reinterpret_cast<const float4*>(g_y  + base * DINNER);
    const float4* y4b = reinterpret_cast<const float4*>(g_y2 + base * DINNER);
    const float4* y4c = reinterpret_cast<const float4*>(g_y3 + base * DINNER);
    const float4* y4d = reinterpret_cast<const float4*>(g_y4 + base * DINNER);
    const float4* x4  = reinterpret_cast<const float4*>(g_x  + base * DINNER);
    const float4* z4  = reinterpret_cast<const float4*>(g_zx + base * DPROJ);
    float4* o4 = reinterpret_cast<float4*>(g_ygn + base * DINNER);
    uint2* h4 = reinterpret_cast<uint2*>(g_hygn + base * DINNER);

    float ss = 0.f;
#pragma unroll
    for (int it = 0; it < 2; it++) {
        int c4 = tid + it * 256;
        float dd = Dp[c4 >> 4];
        float4 a = y4a[c4], b = y4b[c4], c = y4c[c4], d = y4d[c4];
        float4 x = x4[c4], z = z4[c4];
        float4 r;
        r.x = (a.x + b.x + c.x + d.x + dd * x.x) * silu_f(z.x);
        r.y = (a.y + b.y + c.y + d.y + dd * x.y) * silu_f(z.y);
        r.z = (a.z + b.z + c.z + d.z + dd * x.z) * silu_f(z.z);
        r.w = (a.w + b.w + c.w + d.w + dd * x.w) * silu_f(z.w);
        o4[c4] = r;
        ss += r.x * r.x + r.y * r.y + r.z * r.z + r.w * r.w;
    }
    __shared__ float red[8];
#pragma unroll
    for (int o = 16; o; o >>= 1) ss += __shfl_xor_sync(0xffffffffu, ss, o);
    if ((tid & 31) == 0) red[tid >> 5] = ss;
    __syncthreads();
    if (tid < 8) {
        float v = red[tid];
#pragma unroll
        for (int o = 4; o; o >>= 1) v += __shfl_xor_sync(0xffu, v, o);
        if (tid == 0) red[0] = v;
    }
    __syncthreads();
    const float scale = rsqrtf(red[0] * (1.f / DINNER) + 1e-5f);
    const float4* nw4 = reinterpret_cast<const float4*>(nw);
#pragma unroll
    for (int it = 0; it < 2; it++) {
        int c4 = tid + it * 256;
        float4 r = o4[c4], w = nw4[c4];
        r.x *= scale * w.x; r.y *= scale * w.y; r.z *= scale * w.z; r.w *= scale * w.w;
        h4[c4] = f4_to_h4(r);
    }
}

// ---------------- launch ----------------
extern "C" void kernel_launch(void* const* d_in, const int* in_sizes, int n_in,
                              void* d_out, int out_size)
{
    const float* u         = (const float*)d_in[0];
    const float* W_in_f    = (const float*)d_in[1];
    const float* W_in_b    = (const float*)d_in[2];
    const float* conv_w_f  = (const float*)d_in[3];
    const float* conv_b_f  = (const float*)d_in[4];
    const float* conv_w_b  = (const float*)d_in[5];
    const float* conv_b_b  = (const float*)d_in[6];
    const float* dt_bias_f = (const float*)d_in[7];
    const float* dt_bias_b = (const float*)d_in[8];
    const float* A_log_f   = (const float*)d_in[9];
    const float* A_log_b   = (const float*)d_in[10];
    const float* D_f       = (const float*)d_in[11];
    const float* D_b       = (const float*)d_in[12];
    const float* norm_w_f  = (const float*)d_in[13];
    const float* norm_w_b  = (const float*)d_in[14];
    const float* W_out_f   = (const float*)d_in[15];
    const float* W_out_b   = (const float*)d_in[16];
    const float* W_out     = (const float*)d_in[17];

    static int attr_done = 0;
    if (!attr_done) {
        cudaFuncSetAttribute(gemm_hp, cudaFuncAttributeMaxDynamicSharedMemorySize, GEMM_SMEM);
        attr_done = 1;
    }

    float *zx;
    __half *hWin, *hWoutF, *hWoutB, *hWout, *hu, *hygn, *hG;
    cudaGetSymbolAddress((void**)&zx,     g_zx);
    cudaGetSymbolAddress((void**)&hWin,   g_hWin);
    cudaGetSymbolAddress((void**)&hWoutF, g_hWoutF);
    cudaGetSymbolAddress((void**)&hWoutB, g_hWoutB);
    cudaGetSymbolAddress((void**)&hWout,  g_hWout);
    cudaGetSymbolAddress((void**)&hu,     g_hu);
    cudaGetSymbolAddress((void**)&hygn,   g_hygn);
    cudaGetSymbolAddress((void**)&hG,     g_hG);

    // 0) fp32 -> fp16 conversions (weights + u)
    cvt6_kernel<<<1024, 256>>>(W_in_f, W_in_b, W_out_f, W_out_b, W_out, u);

    // 1) in_proj, both directions (z=dir; flip A rows when z==1)
    gemm_hp<<<dim3((DPROJ + 127) / 128, L_SEQ / 128, 2), 256, GEMM_SMEM>>>(
        hu, DMODEL, 1, hWin, hWin + (size_t)DPROJ * DMODEL, DMODEL, zx, DPROJ,
        L_SEQ, DPROJ, DMODEL, 0, (long)L_SEQ * DPROJ, 0);

    // 2) conv + silu + dt/dA/dtx
    prep_kernel<<<dim3(L_SEQ, 2), 256>>>(conv_w_f, conv_b_f, conv_w_b, conv_b_b,
                                         dt_bias_f, dt_bias_b, A_log_f, A_log_b);

    // 3) time-split scan: local chunks (64-thread blocks), carry chain, correction
    scan_kernel<<<dim3(16, 32, 2), 64>>>();
    chain_kernel<<<dim3(NH, 2), 256>>>();
    corr_kernel<<<dim3(12, NH, 2), 256>>>();

    // 4) gate + rmsnorm -> fp16 ygn
    gate_kernel<<<dim3(L_SEQ, 2), 256>>>(D_f, D_b, norm_w_f, norm_w_b);

    // 5) out projections, epi=1 fuses silu + concat + flip into g_hG
    gemm_hp<<<dim3(DMODEL / 128, L_SEQ / 128, 2), 256, GEMM_SMEM>>>(
        hygn, DINNER, 0, hWoutF, hWoutB, DINNER, zx /*unused*/, DMODEL,
        L_SEQ, DMODEL, DINNER, (long)L_SEQ * DINNER, 0, 1);

    // 6) final projection
    gemm_hp<<<dim3(DMODEL / 128, L_SEQ / 128, 1), 256, GEMM_SMEM>>>(
        hG, 2 * DMODEL, 0, hWout, hWout, 2 * DMODEL, (float*)d_out, DMODEL,
        L_SEQ, DMODEL, 2 * DMODEL, 0, 0, 0);
}